// round 15
// baseline (speedup 1.0000x reference)
#include <cuda_runtime.h>
#include <math.h>

#define NKNOT 1024
#define NW    1020          // NUM_KNOTS - DEGREE - 1

// fp32 images of +/-pi (np.linspace endpoints after float32 cast)
#define T_LO (-3.14159274101257324218750f)
#define T_HI ( 3.14159274101257324218750f)

// 1023/(2*pi) split hi+lo (hi = correctly-rounded fp32, lo = residual)
#define INVH_HI 162.81578063964843750f
#define INVH_LO (-8.2343605185432045e-08f)
#define S_OFF   511.5f       // pi * 1023/(2*pi), exactly representable

#define THREADS 256
#define ELEMS   4
#define QENT    256          // entries per shifted copy (e = j0>>2, j0 <= 1023)

__global__ __launch_bounds__(THREADS) void bspline_act_kernel(
    const float* __restrict__ x,
    const float* __restrict__ w,
    float* __restrict__ out)
{
    // Conceptual padded vector s_big[j+4] = w[j] (zeros at [0..3] and >= 1024).
    // Quad table: copy c, entry e holds s_big[4e+c .. 4e+c+3], so the 4 taps of
    // interval i (j0 = i+1) are ONE aligned LDS.128: s_quad[(j0&3)*QENT + (j0>>2)].
    __shared__ float4 s_quad[4 * QENT];   // 16 KB

    const int tid  = threadIdx.x;
    const int base = (blockIdx.x * THREADS + tid) * ELEMS;

    // ---- prefetch x FIRST: its DRAM/L2 latency overlaps prologue + BAR ----
    float4 xv = *reinterpret_cast<const float4*>(x + base);

    // ---- prologue: copy-shaped, uniform control flow (no shfl, no divergence) ----
    {
        const float4* w4 = reinterpret_cast<const float4*>(w);
        const float4  z  = make_float4(0.f, 0.f, 0.f, 0.f);

        // thread t holds s_big slots t and t+1 (slot k = s_big[4k..4k+3]):
        //   slot 0 = zeros, slots 1..255 = w4[k-1], slot 256 = zeros.
        float4 lo = (tid >= 1)   ? w4[tid - 1] : z;   // independent LDG
        float4 hi = (tid <= 254) ? w4[tid]     : z;   // independent LDG

        s_quad[0 * QENT + tid] = lo;                                          // c=0
        s_quad[1 * QENT + tid] = make_float4(lo.y, lo.z, lo.w, hi.x);         // c=1
        s_quad[2 * QENT + tid] = make_float4(lo.z, lo.w, hi.x, hi.y);         // c=2
        s_quad[3 * QENT + tid] = make_float4(lo.w, hi.x, hi.y, hi.z);         // c=3
    }
    __syncthreads();

    float xs[4] = {xv.x, xv.y, xv.z, xv.w};
    float r[4];

#pragma unroll
    for (int e = 0; e < 4; e++) {
        float xx = xs[e];

        // interval index
        float s1 = fmaf(xx, INVH_HI, S_OFF);
        int i = (int)s1;
        i = min(max(i, 0), NKNOT - 2);

        // taps: ONE aligned LDS.128 (depends only on i; overlaps the N-polys)
        int j0 = i + 1;                          // 1..1023
        float4 q = s_quad[(j0 & 3) * QENT + (j0 >> 2)];

        // compensated local coordinate: 511.5 - i exact; lo-term fixes INVH_HI's
        // representation error. u accurate to ~1e-7 vs ideal uniform grid.
        float offi = S_OFF - (float)i;
        float u = fmaf(xx, INVH_LO, fmaf(xx, INVH_HI, offi));

        // uniform cubic B-spline blend
        const float SIXTH = 0.16666666666666666f;
        float omu = 1.0f - u;
        float u2  = u * u;
        float u3  = u2 * u;
        float N0 = omu * omu * omu * SIXTH;
        float N1 = fmaf(3.0f, u3, fmaf(-6.0f, u2, 4.0f)) * SIXTH;
        float N2 = fmaf(-3.0f, u3, fmaf(3.0f, u2, fmaf(3.0f, u, 1.0f))) * SIXTH;
        float N3 = u3 * SIXTH;

        // balanced dot: FMA-tree depth 3
        float p0 = fmaf(N0, q.x, N1 * q.y);
        float p1 = fmaf(N2, q.z, N3 * q.w);
        float acc = p0 + p1;

        r[e] = (xx >= T_LO && xx < T_HI) ? acc : 0.0f;
    }

    *reinterpret_cast<float4*>(out + base) = make_float4(r[0], r[1], r[2], r[3]);
}

extern "C" void kernel_launch(void* const* d_in, const int* in_sizes, int n_in,
                              void* d_out, int out_size) {
    const float* x = (const float*)d_in[0];
    const float* w = (const float*)d_in[1];
    float* out = (float*)d_out;
    int n = in_sizes[0];                         // 262144
    int blocks = n / (THREADS * ELEMS);          // 256, exact cover
    bspline_act_kernel<<<blocks, THREADS>>>(x, w, out);
}

// round 16
// speedup vs baseline: 1.0914x; 1.0914x over previous
#include <cuda_runtime.h>
#include <math.h>

#define NKNOT 1024
#define NW    1020          // NUM_KNOTS - DEGREE - 1

// fp32 images of +/-pi (np.linspace endpoints after float32 cast)
#define T_LO (-3.14159274101257324218750f)
#define T_HI ( 3.14159274101257324218750f)

// 1023/(2*pi) split hi+lo (hi = correctly-rounded fp32, lo = residual)
#define INVH_HI 162.81578063964843750f
#define INVH_LO (-8.2343605185432045e-08f)
#define S_OFF   511.5f       // pi * 1023/(2*pi), exactly representable

#define THREADS 256
#define ELEMS   4
#define TBL     1032         // 4 zero + 1020 weights + 8 zero

__global__ __launch_bounds__(THREADS) void bspline_act_kernel(
    const float* __restrict__ x,
    const float* __restrict__ w,
    float* __restrict__ out)
{
    // s_big[j+4] = w[j]; zeros at [0..3] and [1024..1031].
    // Tap k of interval i is w[i-3+k] = s_big[i+1+k] — always in range, no clamps.
    __shared__ float s_big[TBL];

    const int tid  = threadIdx.x;
    const int base = (blockIdx.x * THREADS + tid) * ELEMS;

    // ---- prefetch x FIRST: its DRAM/L2 latency overlaps the prologue + BAR ----
    float4 xv = *reinterpret_cast<const float4*>(x + base);

    // ---- prologue: pure copy, one float4 per thread ----
    if (tid < NW / 4) {                                         // 255 threads
        reinterpret_cast<float4*>(s_big + 4)[tid] =
            reinterpret_cast<const float4*>(w)[tid];
    } else {                                                    // tid == 255: zero pads
        float4 z = make_float4(0.f, 0.f, 0.f, 0.f);
        reinterpret_cast<float4*>(s_big)[0]   = z;              // [0..3]
        reinterpret_cast<float4*>(s_big)[256] = z;              // [1024..1027]
        reinterpret_cast<float4*>(s_big)[257] = z;              // [1028..1031]
    }
    __syncthreads();

    float xs[4] = {xv.x, xv.y, xv.z, xv.w};
    float r[4];

#pragma unroll
    for (int e = 0; e < 4; e++) {
        float xx = xs[e];

        // interval index
        float s1 = fmaf(xx, INVH_HI, S_OFF);
        int i = (int)s1;
        i = min(max(i, 0), NKNOT - 2);

        // compensated local coordinate: 511.5 - i exact; lo-term fixes INVH_HI's
        // representation error. u accurate to ~1e-7 vs ideal uniform grid.
        float offi = S_OFF - (float)i;
        float u = fmaf(xx, INVH_LO, fmaf(xx, INVH_HI, offi));

        // 4 unconditional weight taps (parallel LDS)
        float w0 = s_big[i + 1];
        float w1 = s_big[i + 2];
        float w2 = s_big[i + 3];
        float w3 = s_big[i + 4];

        // uniform cubic B-spline blend
        const float SIXTH = 0.16666666666666666f;
        float omu = 1.0f - u;
        float u2  = u * u;
        float u3  = u2 * u;
        float N0 = omu * omu * omu * SIXTH;
        float N1 = fmaf(3.0f, u3, fmaf(-6.0f, u2, 4.0f)) * SIXTH;
        float N2 = fmaf(-3.0f, u3, fmaf(3.0f, u2, fmaf(3.0f, u, 1.0f))) * SIXTH;
        float N3 = u3 * SIXTH;

        float acc = fmaf(N0, w0, fmaf(N1, w1, fmaf(N2, w2, N3 * w3)));
        r[e] = (xx >= T_LO && xx < T_HI) ? acc : 0.0f;
    }

    *reinterpret_cast<float4*>(out + base) = make_float4(r[0], r[1], r[2], r[3]);
}

extern "C" void kernel_launch(void* const* d_in, const int* in_sizes, int n_in,
                              void* d_out, int out_size) {
    const float* x = (const float*)d_in[0];
    const float* w = (const float*)d_in[1];
    float* out = (float*)d_out;
    int n = in_sizes[0];                         // 262144
    int blocks = n / (THREADS * ELEMS);          // 256, exact cover
    bspline_act_kernel<<<blocks, THREADS>>>(x, w, out);
}